// round 1
// baseline (speedup 1.0000x reference)
#include <cuda_runtime.h>
#include <cuda_bf16.h>
#include <cstdint>

// BundleAdjustmentModel: project N points into V camera views.
//   out[v][n] = (u, v) with cam = R_v * p_n + t_v, perspective divide by safe_z.
// HBM-write-bound: 256 MB out, ~6 MB in.

#define V_VIEWS 64

__constant__ float c_dummy; // (unused; keeps nvcc happy about empty TU sections)

__global__ __launch_bounds__(256)
void bundle_project_kernel(const float* __restrict__ points,          // [N,3]
                           const float* __restrict__ euler,           // [V,3]
                           const float* __restrict__ txy,             // [V,2]
                           const float* __restrict__ tdepth,          // [V]
                           const float* __restrict__ focal_raw,       // [1]
                           const int*   __restrict__ cx_p,            // scalar
                           const int*   __restrict__ cy_p,            // scalar
                           float* __restrict__ out,                   // [V,N,2]
                           int n_pts)
{
    // Per-view params in shared: 12 floats per view (R[9], tx, ty, tz), 48B rows
    // => 16B-aligned rows, read back as 3x LDS.128 broadcast.
    __shared__ __align__(16) float sP[V_VIEWS][12];
    __shared__ float s_focal, s_cx, s_cy;

    const int tid = threadIdx.x;

    if (tid < V_VIEWS) {
        const float ex = euler[tid * 3 + 0];
        const float ey = euler[tid * 3 + 1];
        const float ez = euler[tid * 3 + 2];
        float cxa = cosf(ex), sxa = sinf(ex);
        float cya = cosf(ey), sya = sinf(ey);
        float cza = cosf(ez), sza = sinf(ez);
        // R = Rx * Ry * Rz
        sP[tid][0] = cya * cza;
        sP[tid][1] = -cya * sza;
        sP[tid][2] = sya;
        sP[tid][3] = cxa * sza + sxa * sya * cza;
        sP[tid][4] = cxa * cza - sxa * sya * sza;
        sP[tid][5] = -sxa * cya;
        sP[tid][6] = sxa * sza - cxa * sya * cza;
        sP[tid][7] = sxa * cza + cxa * sya * sza;
        sP[tid][8] = cxa * cya;
        sP[tid][9]  = txy[tid * 2 + 0];
        sP[tid][10] = txy[tid * 2 + 1];
        // depth = softplus(raw) + 0.25 ; translation z = -depth
        const float d = tdepth[tid];
        sP[tid][11] = -(log1pf(expf(d)) + 0.25f);
    }
    if (tid == 0) {
        s_focal = log1pf(expf(focal_raw[0])) + 50.0f;
        s_cx = (float)cx_p[0];
        s_cy = (float)cy_p[0];
    }
    __syncthreads();

    // Each thread owns two adjacent points -> one STG.128 per view iteration.
    const int i = blockIdx.x * blockDim.x + tid;
    const int n0 = 2 * i;
    if (n0 >= n_pts) return;
    const bool has2 = (n0 + 1) < n_pts;

    const float p0x = points[(size_t)n0 * 3 + 0];
    const float p0y = points[(size_t)n0 * 3 + 1];
    const float p0z = points[(size_t)n0 * 3 + 2];
    float p1x = 0.f, p1y = 0.f, p1z = 0.f;
    if (has2) {
        p1x = points[(size_t)(n0 + 1) * 3 + 0];
        p1y = points[(size_t)(n0 + 1) * 3 + 1];
        p1z = points[(size_t)(n0 + 1) * 3 + 2];
    }

    const float f   = s_focal;
    const float cxf = s_cx;
    const float cyf = s_cy;
    const float Z_EPS = 1e-4f;

    #pragma unroll 4
    for (int v = 0; v < V_VIEWS; v++) {
        const float4* pr = reinterpret_cast<const float4*>(&sP[v][0]);
        const float4 r0 = pr[0];   // R00 R01 R02 R10
        const float4 r1 = pr[1];   // R11 R12 R20 R21
        const float4 r2 = pr[2];   // R22 tx  ty  tz

        // point 0
        float x0 = fmaf(r0.x, p0x, fmaf(r0.y, p0y, fmaf(r0.z, p0z, r2.y)));
        float y0 = fmaf(r0.w, p0x, fmaf(r1.x, p0y, fmaf(r1.y, p0z, r2.z)));
        float z0 = fmaf(r1.z, p0x, fmaf(r1.w, p0y, fmaf(r2.x, p0z, r2.w)));
        float sz0 = (z0 >= 0.0f) ? fmaxf(z0, Z_EPS) : fminf(z0, -Z_EPS);
        float inv0 = __fdividef(1.0f, sz0);
        float u0 = fmaf(-f * x0, inv0, cxf);
        float w0 = fmaf( f * y0, inv0, cyf);

        // point 1
        float x1 = fmaf(r0.x, p1x, fmaf(r0.y, p1y, fmaf(r0.z, p1z, r2.y)));
        float y1 = fmaf(r0.w, p1x, fmaf(r1.x, p1y, fmaf(r1.y, p1z, r2.z)));
        float z1 = fmaf(r1.z, p1x, fmaf(r1.w, p1y, fmaf(r2.x, p1z, r2.w)));
        float sz1 = (z1 >= 0.0f) ? fmaxf(z1, Z_EPS) : fminf(z1, -Z_EPS);
        float inv1 = __fdividef(1.0f, sz1);
        float u1 = fmaf(-f * x1, inv1, cxf);
        float w1 = fmaf( f * y1, inv1, cyf);

        float* base = out + ((size_t)v * n_pts + n0) * 2;
        if (has2) {
            // two adjacent (u,v) pairs -> single 16B store
            float4 pack = make_float4(u0, w0, u1, w1);
            *reinterpret_cast<float4*>(base) = pack;
        } else {
            float2 pack = make_float2(u0, w0);
            *reinterpret_cast<float2*>(base) = pack;
        }
    }
}

extern "C" void kernel_launch(void* const* d_in, const int* in_sizes, int n_in,
                              void* d_out, int out_size) {
    const float* points    = (const float*)d_in[0];
    const float* euler     = (const float*)d_in[1];
    const float* txy       = (const float*)d_in[2];
    const float* tdepth    = (const float*)d_in[3];
    const float* focal_raw = (const float*)d_in[4];
    const int*   cx_p      = (const int*)d_in[5];
    const int*   cy_p      = (const int*)d_in[6];
    float*       out       = (float*)d_out;

    const int n_pts = in_sizes[0] / 3;       // points is [N,3]
    const int pairs = (n_pts + 1) / 2;       // 2 points per thread
    const int threads = 256;
    const int blocks = (pairs + threads - 1) / threads;

    bundle_project_kernel<<<blocks, threads>>>(points, euler, txy, tdepth,
                                               focal_raw, cx_p, cy_p,
                                               out, n_pts);
}

// round 2
// speedup vs baseline: 1.1243x; 1.1243x over previous
#include <cuda_runtime.h>
#include <cuda_bf16.h>
#include <cstdint>

// BundleAdjustmentModel: project N points into V=64 camera views.
// out[v][n] = (u,v);  cam = R_v p + t_v;  u = -f*x/sz + cx, v = f*y/sz + cy.
// HBM-write-bound (256 MB out). Focal folded into rotation rows at setup:
//   A = -f*R0, tA = -f*tx   -> u = (A.p + tA)*inv + cx
//   B =  f*R1, tB =  f*ty   -> v = (B.p + tB)*inv + cy
//   C =    R2, tC = -depth  -> z = C.p + tC

#define V_VIEWS 64

__global__ __launch_bounds__(128)
void bundle_project_kernel(const float* __restrict__ points,     // [N,3]
                           const float* __restrict__ euler,      // [V,3]
                           const float* __restrict__ txy,        // [V,2]
                           const float* __restrict__ tdepth,     // [V]
                           const float* __restrict__ focal_raw,  // [1]
                           const int*   __restrict__ cx_p,
                           const int*   __restrict__ cy_p,
                           float* __restrict__ out,              // [V,N,2]
                           int n_pts)
{
    // 12 floats/view, 48B rows (16B-aligned) -> 3x LDS.128 broadcast per view.
    // layout: [Ax Ay Az Bx][By Bz Cx Cy][Cz tA tB tC]
    __shared__ __align__(16) float sP[V_VIEWS][12];
    __shared__ float s_cx, s_cy;

    const int tid = threadIdx.x;

    if (tid < V_VIEWS) {
        const float f = log1pf(expf(focal_raw[0])) + 50.0f;
        const float ex = euler[tid * 3 + 0];
        const float ey = euler[tid * 3 + 1];
        const float ez = euler[tid * 3 + 2];
        float cxa = cosf(ex), sxa = sinf(ex);
        float cya = cosf(ey), sya = sinf(ey);
        float cza = cosf(ez), sza = sinf(ez);
        // R = Rx * Ry * Rz
        float R00 = cya * cza,                  R01 = -cya * sza,                 R02 = sya;
        float R10 = cxa * sza + sxa * sya * cza, R11 = cxa * cza - sxa * sya * sza, R12 = -sxa * cya;
        float R20 = sxa * sza - cxa * sya * cza, R21 = sxa * cza + cxa * sya * sza, R22 = cxa * cya;

        sP[tid][0] = -f * R00;  sP[tid][1] = -f * R01;  sP[tid][2] = -f * R02;
        sP[tid][3] =  f * R10;  sP[tid][4] =  f * R11;  sP[tid][5] =  f * R12;
        sP[tid][6] =  R20;      sP[tid][7] =  R21;      sP[tid][8] =  R22;
        sP[tid][9]  = -f * txy[tid * 2 + 0];                 // tA
        sP[tid][10] =  f * txy[tid * 2 + 1];                 // tB
        const float d = tdepth[tid];
        sP[tid][11] = -(log1pf(expf(d)) + 0.25f);            // tC = -depth
    }
    if (tid == 0) {
        s_cx = (float)cx_p[0];
        s_cy = (float)cy_p[0];
    }
    __syncthreads();

    const int i = blockIdx.x * blockDim.x + tid;
    const int n0 = 2 * i;
    if (n0 >= n_pts) return;
    const bool has2 = (n0 + 1) < n_pts;

    const float p0x = points[(size_t)n0 * 3 + 0];
    const float p0y = points[(size_t)n0 * 3 + 1];
    const float p0z = points[(size_t)n0 * 3 + 2];
    float p1x = 0.f, p1y = 0.f, p1z = 0.f;
    if (has2) {
        p1x = points[(size_t)(n0 + 1) * 3 + 0];
        p1y = points[(size_t)(n0 + 1) * 3 + 1];
        p1z = points[(size_t)(n0 + 1) * 3 + 2];
    }

    const float cxf = s_cx;
    const float cyf = s_cy;
    const float Z_EPS = 1e-4f;
    const size_t view_stride = (size_t)n_pts * 2;   // floats per view slab

    float* base = out + (size_t)n0 * 2;

    #pragma unroll 8
    for (int v = 0; v < V_VIEWS; v++) {
        const float4* pr = reinterpret_cast<const float4*>(&sP[v][0]);
        const float4 r0 = pr[0];   // Ax Ay Az Bx
        const float4 r1 = pr[1];   // By Bz Cx Cy
        const float4 r2 = pr[2];   // Cz tA tB tC

        // point 0
        float a0 = fmaf(r0.x, p0x, fmaf(r0.y, p0y, fmaf(r0.z, p0z, r2.y)));
        float b0 = fmaf(r0.w, p0x, fmaf(r1.x, p0y, fmaf(r1.y, p0z, r2.z)));
        float z0 = fmaf(r1.z, p0x, fmaf(r1.w, p0y, fmaf(r2.x, p0z, r2.w)));
        float m0 = fmaxf(fabsf(z0), Z_EPS);
        float sz0 = (z0 >= 0.0f) ? m0 : -m0;
        float inv0 = __fdividef(1.0f, sz0);
        float u0 = fmaf(a0, inv0, cxf);
        float w0 = fmaf(b0, inv0, cyf);

        // point 1
        float a1 = fmaf(r0.x, p1x, fmaf(r0.y, p1y, fmaf(r0.z, p1z, r2.y)));
        float b1 = fmaf(r0.w, p1x, fmaf(r1.x, p1y, fmaf(r1.y, p1z, r2.z)));
        float z1 = fmaf(r1.z, p1x, fmaf(r1.w, p1y, fmaf(r2.x, p1z, r2.w)));
        float m1 = fmaxf(fabsf(z1), Z_EPS);
        float sz1 = (z1 >= 0.0f) ? m1 : -m1;
        float inv1 = __fdividef(1.0f, sz1);
        float u1 = fmaf(a1, inv1, cxf);
        float w1 = fmaf(b1, inv1, cyf);

        if (has2) {
            __stcs(reinterpret_cast<float4*>(base), make_float4(u0, w0, u1, w1));
        } else {
            __stcs(reinterpret_cast<float2*>(base), make_float2(u0, w0));
        }
        base += view_stride;
    }
}

extern "C" void kernel_launch(void* const* d_in, const int* in_sizes, int n_in,
                              void* d_out, int out_size) {
    const float* points    = (const float*)d_in[0];
    const float* euler     = (const float*)d_in[1];
    const float* txy       = (const float*)d_in[2];
    const float* tdepth    = (const float*)d_in[3];
    const float* focal_raw = (const float*)d_in[4];
    const int*   cx_p      = (const int*)d_in[5];
    const int*   cy_p      = (const int*)d_in[6];
    float*       out       = (float*)d_out;

    const int n_pts = in_sizes[0] / 3;       // points is [N,3]
    const int pairs = (n_pts + 1) / 2;       // 2 points per thread
    const int threads = 128;                 // smaller blocks -> better SM balance
    const int blocks = (pairs + threads - 1) / threads;

    bundle_project_kernel<<<blocks, threads>>>(points, euler, txy, tdepth,
                                               focal_raw, cx_p, cy_p,
                                               out, n_pts);
}

// round 5
// speedup vs baseline: 1.2063x; 1.0729x over previous
#include <cuda_runtime.h>
#include <cuda_bf16.h>
#include <cstdint>

// BundleAdjustmentModel: project N points into V=64 camera views.
// out[v][n] = (u,v);  cam = R_v p + t_v;  u = -f*x/sz + cx, v = f*y/sz + cy.
// HBM-write-bound (256 MB out). View-tiled via 1D grid decomposition:
// block bx -> (chunk = bx % chunks, vgroup = bx / chunks); each block does
// VG=8 views x 256 points so concurrent DRAM write streams cluster.
// Focal folded into rotation rows:
//   A = -f*R0, tA = -f*tx   -> u = (A.p + tA)*inv + cx
//   B =  f*R1, tB =  f*ty   -> v = (B.p + tB)*inv + cy
//   C =    R2, tC = -depth  -> z = C.p + tC
// safe-z via clamp: 1/safe_z == clamp(1/z, -1/eps, +1/eps)

#define V_VIEWS 64
#define VG 8            // views per block

__global__ __launch_bounds__(128)
void bundle_project_kernel(const float* __restrict__ points,     // [N,3]
                           const float* __restrict__ euler,      // [V,3]
                           const float* __restrict__ txy,        // [V,2]
                           const float* __restrict__ tdepth,     // [V]
                           const float* __restrict__ focal_raw,  // [1]
                           const int*   __restrict__ cx_p,
                           const int*   __restrict__ cy_p,
                           float* __restrict__ out,              // [V,N,2]
                           int n_pts,
                           int chunks)
{
    // 12 floats/view, 48B rows (16B-aligned) -> 3x LDS.128 broadcast per view.
    // layout: [Ax Ay Az Bx][By Bz Cx Cy][Cz tA tB tC]
    __shared__ __align__(16) float sP[VG][12];
    __shared__ float s_cx, s_cy;

    const int tid   = threadIdx.x;
    const int chunk = blockIdx.x % chunks;
    const int vbase = (blockIdx.x / chunks) * VG;

    if (tid < VG) {
        const int v = vbase + tid;
        const float f = log1pf(expf(focal_raw[0])) + 50.0f;
        const float ex = euler[v * 3 + 0];
        const float ey = euler[v * 3 + 1];
        const float ez = euler[v * 3 + 2];
        float cxa = cosf(ex), sxa = sinf(ex);
        float cya = cosf(ey), sya = sinf(ey);
        float cza = cosf(ez), sza = sinf(ez);
        // R = Rx * Ry * Rz
        float R00 = cya * cza,                   R01 = -cya * sza,                  R02 = sya;
        float R10 = cxa * sza + sxa * sya * cza, R11 = cxa * cza - sxa * sya * sza, R12 = -sxa * cya;
        float R20 = sxa * sza - cxa * sya * cza, R21 = sxa * cza + cxa * sya * sza, R22 = cxa * cya;

        sP[tid][0] = -f * R00;  sP[tid][1] = -f * R01;  sP[tid][2] = -f * R02;
        sP[tid][3] =  f * R10;  sP[tid][4] =  f * R11;  sP[tid][5] =  f * R12;
        sP[tid][6] =  R20;      sP[tid][7] =  R21;      sP[tid][8] =  R22;
        sP[tid][9]  = -f * txy[v * 2 + 0];                  // tA
        sP[tid][10] =  f * txy[v * 2 + 1];                  // tB
        const float d = tdepth[v];
        sP[tid][11] = -(log1pf(expf(d)) + 0.25f);           // tC = -depth
    }
    if (tid == 0) {
        s_cx = (float)cx_p[0];
        s_cy = (float)cy_p[0];
    }
    __syncthreads();

    const int i = chunk * blockDim.x + tid;
    const int n0 = 2 * i;
    if (n0 >= n_pts) return;
    const bool has2 = (n0 + 1) < n_pts;

    const float p0x = points[(size_t)n0 * 3 + 0];
    const float p0y = points[(size_t)n0 * 3 + 1];
    const float p0z = points[(size_t)n0 * 3 + 2];
    float p1x = 0.f, p1y = 0.f, p1z = 0.f;
    if (has2) {
        p1x = points[(size_t)(n0 + 1) * 3 + 0];
        p1y = points[(size_t)(n0 + 1) * 3 + 1];
        p1z = points[(size_t)(n0 + 1) * 3 + 2];
    }

    const float cxf = s_cx;
    const float cyf = s_cy;
    const float INV_CLAMP = 1.0f / 1e-4f;    // 1/Z_EPS
    const size_t view_stride = (size_t)n_pts * 2;   // floats per view slab

    float* base = out + ((size_t)vbase * n_pts + n0) * 2;

    #pragma unroll
    for (int v = 0; v < VG; v++) {
        const float4* pr = reinterpret_cast<const float4*>(&sP[v][0]);
        const float4 r0 = pr[0];   // Ax Ay Az Bx
        const float4 r1 = pr[1];   // By Bz Cx Cy
        const float4 r2 = pr[2];   // Cz tA tB tC

        // point 0
        float a0 = fmaf(r0.x, p0x, fmaf(r0.y, p0y, fmaf(r0.z, p0z, r2.y)));
        float b0 = fmaf(r0.w, p0x, fmaf(r1.x, p0y, fmaf(r1.y, p0z, r2.z)));
        float z0 = fmaf(r1.z, p0x, fmaf(r1.w, p0y, fmaf(r2.x, p0z, r2.w)));
        float inv0 = __fdividef(1.0f, z0);
        inv0 = fminf(fmaxf(inv0, -INV_CLAMP), INV_CLAMP);
        float u0 = fmaf(a0, inv0, cxf);
        float w0 = fmaf(b0, inv0, cyf);

        // point 1
        float a1 = fmaf(r0.x, p1x, fmaf(r0.y, p1y, fmaf(r0.z, p1z, r2.y)));
        float b1 = fmaf(r0.w, p1x, fmaf(r1.x, p1y, fmaf(r1.y, p1z, r2.z)));
        float z1 = fmaf(r1.z, p1x, fmaf(r1.w, p1y, fmaf(r2.x, p1z, r2.w)));
        float inv1 = __fdividef(1.0f, z1);
        inv1 = fminf(fmaxf(inv1, -INV_CLAMP), INV_CLAMP);
        float u1 = fmaf(a1, inv1, cxf);
        float w1 = fmaf(b1, inv1, cyf);

        if (has2) {
            __stcs(reinterpret_cast<float4*>(base), make_float4(u0, w0, u1, w1));
        } else {
            __stcs(reinterpret_cast<float2*>(base), make_float2(u0, w0));
        }
        base += view_stride;
    }
}

extern "C" void kernel_launch(void* const* d_in, const int* in_sizes, int n_in,
                              void* d_out, int out_size) {
    const float* points    = (const float*)d_in[0];
    const float* euler     = (const float*)d_in[1];
    const float* txy       = (const float*)d_in[2];
    const float* tdepth    = (const float*)d_in[3];
    const float* focal_raw = (const float*)d_in[4];
    const int*   cx_p      = (const int*)d_in[5];
    const int*   cy_p      = (const int*)d_in[6];
    float*       out       = (float*)d_out;

    const int n_pts = in_sizes[0] / 3;       // points is [N,3]
    const int pairs = (n_pts + 1) / 2;       // 2 points per thread
    const int threads = 128;
    const int chunks = (pairs + threads - 1) / threads;
    const int blocks = chunks * (V_VIEWS / VG);

    bundle_project_kernel<<<blocks, threads>>>(points, euler, txy, tdepth,
                                               focal_raw, cx_p, cy_p,
                                               out, n_pts, chunks);
}